// round 9
// baseline (speedup 1.0000x reference)
#include <cuda_runtime.h>
#include <math.h>

#define T_DIM 512
#define B_DIM 64
#define I_DIM 512
#define H_DIM 512
#define BH (B_DIM * H_DIM)          // 32768
#define NBLK 128
#define CLU 8                        // CTAs per cluster = one b-group

// SMEM float offsets
#define W_OFF   0                    // 512*64 = 32768 (weight slice [k][j])
#define HT_OFF  32768                // 512*4  = 2048  (h transposed [k][b])
#define RED_OFF 34816                // 8*256  = 2048  (k-partials [kc][c][b]; preamble zw/rw)
#define ZU_OFF  36864                // 512
#define RU_OFF  37376                // 512
#define XZ_OFF  37888                // 2048 ([t][b])
#define XR_OFF  39936                // 2048
#define GZ_OFF  41984                // 16 ([b][4 warp-partials])
#define GR_OFF  42000                // 16
#define SMEM_FLOATS 42016
#define SMEM_BYTES (SMEM_FLOATS * 4) // 168064

typedef unsigned long long ull;

// ---------------- scratch ----------------
__device__ float g_xz[T_DIM * B_DIM];
__device__ float g_xr[T_DIM * B_DIM];

// ---------------- packed f32x2 helpers ----------------
static __device__ __forceinline__ ull pk2(float x) {
    ull r;
    asm("mov.b64 %0, {%1, %1};" : "=l"(r) : "f"(x));
    return r;
}
static __device__ __forceinline__ void fma2(ull& d, ull a, ull b) {
    asm("fma.rn.f32x2 %0, %1, %2, %0;" : "+l"(d) : "l"(a), "l"(b));
}

// ---------------- cluster barrier ----------------
static __device__ __forceinline__ void cluster_sync() {
    asm volatile("barrier.cluster.arrive.aligned;" ::: "memory");
    asm volatile("barrier.cluster.wait.aligned;" ::: "memory");
}

// ---------------- K1: xn = input @ h_w_w^T + h_w_b -> out[t] ----------------
__global__ __launch_bounds__(256) void k_xn(
    const float* __restrict__ A,
    const float* __restrict__ W,
    const float* __restrict__ bias,
    float* __restrict__ C)
{
    __shared__ float As[64 * 17];
    __shared__ float Bs[16 * 64];
    const int bm = blockIdx.y * 64;
    const int bn = blockIdx.x * 64;
    const int tid = threadIdx.x;
    const int tx = tid & 15;
    const int ty = tid >> 4;
    const int r0 = tid >> 2;
    const int c4 = (tid & 3) * 4;

    ull acc[4][2] = {};

    const float* Ap = A + (size_t)(bm + r0) * 512 + c4;
    const float* Wp = W + (size_t)(bn + r0) * 512 + c4;
    float4 a0 = *(const float4*)Ap;
    float4 w0 = *(const float4*)Wp;

    for (int kt = 0; kt < 32; kt++) {
        As[r0 * 17 + c4 + 0] = a0.x;  As[r0 * 17 + c4 + 1] = a0.y;
        As[r0 * 17 + c4 + 2] = a0.z;  As[r0 * 17 + c4 + 3] = a0.w;
        Bs[(c4 + 0) * 64 + r0] = w0.x;  Bs[(c4 + 1) * 64 + r0] = w0.y;
        Bs[(c4 + 2) * 64 + r0] = w0.z;  Bs[(c4 + 3) * 64 + r0] = w0.w;
        __syncthreads();
        if (kt < 31) {
            a0 = *(const float4*)(Ap + (kt + 1) * 16);
            w0 = *(const float4*)(Wp + (kt + 1) * 16);
        }
#pragma unroll
        for (int k = 0; k < 16; k++) {
            ulonglong2 b2 = *(ulonglong2*)&Bs[k * 64 + tx * 4];
#pragma unroll
            for (int i = 0; i < 4; i++) {
                ull aa = pk2(As[(ty * 4 + i) * 17 + k]);
                fma2(acc[i][0], aa, b2.x);
                fma2(acc[i][1], aa, b2.y);
            }
        }
        __syncthreads();
    }
    float4 bv = *(const float4*)(bias + bn + tx * 4);
#pragma unroll
    for (int i = 0; i < 4; i++) {
        float2 lo = *(float2*)&acc[i][0];
        float2 hi = *(float2*)&acc[i][1];
        float4 o = make_float4(lo.x + bv.x, lo.y + bv.y, hi.x + bv.z, hi.y + bv.w);
        *(float4*)(C + (size_t)(bm + ty * 4 + i) * 512 + bn + tx * 4) = o;
    }
}

// ---------------- K2: clustered persistent recurrent scan ----------------
// 16 clusters x 8 CTAs. Cluster = b-group (4 batch rows); CTA = h-slice (64 cols).
// No cross-cluster dependency -> only barrier.cluster per step.
__global__ __launch_bounds__(256, 1) __cluster_dims__(CLU, 1, 1) void k_recur(
    const float* __restrict__ input,
    const float* __restrict__ hidden,
    const float* __restrict__ zw_w, const float* __restrict__ zw_b,
    const float* __restrict__ zu_w, const float* __restrict__ zu_b,
    const float* __restrict__ rw_w, const float* __restrict__ rw_b,
    const float* __restrict__ ru_w, const float* __restrict__ ru_b,
    const float* __restrict__ hu_w, const float* __restrict__ hu_b,
    float* __restrict__ out,          // [T][B][H]: xn on entry, h_t on exit
    float* __restrict__ hfinal, int write_final)
{
    extern __shared__ float smem[];
    float* w_s   = smem + W_OFF;      // [k][j], j=0..63
    float* h_sT  = smem + HT_OFF;     // [k][b], b=0..3
    float* red_s = smem + RED_OFF;    // [kc][c][b]
    float* zu_s  = smem + ZU_OFF;
    float* ru_s  = smem + RU_OFF;
    float* xz_s  = smem + XZ_OFF;     // [t][b]
    float* xr_s  = smem + XR_OFF;
    float* gz_s  = smem + GZ_OFF;     // [b][4]
    float* gr_s  = smem + GR_OFF;

    const int tid = threadIdx.x;
    const int bid = blockIdx.x;
    const int hg = bid & 7;           // h-slice (== cluster rank)
    const int bg = bid >> 3;          // b-group (== cluster id)
    const int b0 = bg * 4;
    const int h0 = hg * 64;
    const int warp = tid >> 5;
    const int lane = tid & 31;

    // persistent weight slice (transposed): w_s[k*64 + j] = hu_w[h0+j][k]
    for (int e = tid; e < 32768; e += 256) {
        int j = e >> 9, k = e & 511;
        w_s[k * 64 + j] = hu_w[(size_t)(h0 + j) * 512 + k];
    }
    for (int e = tid; e < 512; e += 256) {
        zu_s[e] = zu_w[e];
        ru_s[e] = ru_w[e];
    }
    const float zub = zu_b[0], rub = ru_b[0];
    const float zwb = zw_b[0], rwb = rw_b[0];

    // preamble: this block computes xz/xr for t in [hg*64, hg*64+64), its 4 b-rows
    {
        float* zw_s = red_s;
        float* rw_s = red_s + 1024;
        for (int e = tid; e < 512; e += 256) {
            zw_s[e] = zw_w[e];
            rw_s[e] = rw_w[e];
        }
        __syncthreads();
        int tl = tid >> 2, bb = tid & 3;
        int t = hg * 64 + tl;
        const float4* ip = (const float4*)(input + ((size_t)t * 64 + b0 + bb) * 512);
        float az = 0.f, ar = 0.f;
#pragma unroll 8
        for (int i = 0; i < 128; i++) {
            float4 v = ip[i];
            float4 zz = *(float4*)&zw_s[i * 4];
            float4 rr = *(float4*)&rw_s[i * 4];
            az += v.x * zz.x + v.y * zz.y + v.z * zz.z + v.w * zz.w;
            ar += v.x * rr.x + v.y * rr.y + v.z * rr.z + v.w * rr.w;
        }
        g_xz[t * 64 + b0 + bb] = az + zwb;
        g_xr[t * 64 + b0 + bb] = ar + rwb;
    }
    cluster_sync();

    // gather full gate-x slice for this b-group
    for (int e = tid; e < 2048; e += 256) {
        int t = e >> 2, bb = e & 3;
        xz_s[e] = __ldcg(&g_xz[t * 64 + b0 + bb]);
        xr_s[e] = __ldcg(&g_xr[t * 64 + b0 + bb]);
    }

    const int ub = tid >> 6;          // 0..3 (owned batch row)
    const int uh = tid & 63;          // 0..63 (owned col within slice)
    const float hub = hu_b[h0 + uh];
    const int c0 = lane * 2;          // matvec: 2 cols per lane
    const int k0w = warp * 64;        // matvec: 64 k per warp
    float hreg = 0.f;
    __syncthreads();

    for (int t = 0; t < T_DIM; t++) {
        const float* hprev = (t == 0) ? hidden : (out + (size_t)(t - 1) * BH);

        // prefetch own xn
        float xn = __ldcg(out + (size_t)t * BH + (size_t)(b0 + ub) * 512 + h0 + uh);

        // phase 1: load h rows, transpose to [k][b], gate dots from registers
#pragma unroll
        for (int i = 0; i < 2; i++) {
            int e4 = tid + i * 256;
            int bb = e4 >> 7, kq = e4 & 127;
            float4 v = __ldcg((const float4*)(hprev + (size_t)(b0 + bb) * 512 + kq * 4));
            h_sT[(kq * 4 + 0) * 4 + bb] = v.x;
            h_sT[(kq * 4 + 1) * 4 + bb] = v.y;
            h_sT[(kq * 4 + 2) * 4 + bb] = v.z;
            h_sT[(kq * 4 + 3) * 4 + bb] = v.w;
            float4 zz = *(float4*)&zu_s[kq * 4];
            float4 rr = *(float4*)&ru_s[kq * 4];
            float az = v.x * zz.x + v.y * zz.y + v.z * zz.z + v.w * zz.w;
            float ar = v.x * rr.x + v.y * rr.y + v.z * rr.z + v.w * rr.w;
#pragma unroll
            for (int o = 16; o > 0; o >>= 1) {
                az += __shfl_xor_sync(0xffffffffu, az, o);
                ar += __shfl_xor_sync(0xffffffffu, ar, o);
            }
            if (lane == 0) {
                gz_s[bb * 4 + (warp & 3)] = az;
                gr_s[bb * 4 + (warp & 3)] = ar;
            }
        }
        __syncthreads();

        // phase 2: matvec — warp owns 64 k, lane owns 2 cols, all 4 b packed
        {
            ull a01_0 = 0, a23_0 = 0, a01_1 = 0, a23_1 = 0;
#pragma unroll 8
            for (int k = 0; k < 64; k++) {
                int kk = k0w + k;
                ulonglong2 hv = *(ulonglong2*)&h_sT[kk * 4];   // (b0,b1),(b2,b3)
                ull w0p = pk2(w_s[kk * 64 + c0]);
                ull w1p = pk2(w_s[kk * 64 + c0 + 1]);
                fma2(a01_0, hv.x, w0p);
                fma2(a23_0, hv.y, w0p);
                fma2(a01_1, hv.x, w1p);
                fma2(a23_1, hv.y, w1p);
            }
            *(ull*)&red_s[warp * 256 + c0 * 4 + 0] = a01_0;
            *(ull*)&red_s[warp * 256 + c0 * 4 + 2] = a23_0;
            *(ull*)&red_s[warp * 256 + (c0 + 1) * 4 + 0] = a01_1;
            *(ull*)&red_s[warp * 256 + (c0 + 1) * 4 + 2] = a23_1;
        }
        __syncthreads();

        // phase 3: reduce 8 k-partials + gates + update (1 element/thread)
        {
            float m = hub;
#pragma unroll
            for (int w8 = 0; w8 < 8; w8++)
                m += red_s[w8 * 256 + uh * 4 + ub];
            float az = xz_s[t * 4 + ub] + zub
                     + gz_s[ub * 4 + 0] + gz_s[ub * 4 + 1]
                     + gz_s[ub * 4 + 2] + gz_s[ub * 4 + 3];
            float ar = xr_s[t * 4 + ub] + rub
                     + gr_s[ub * 4 + 0] + gr_s[ub * 4 + 1]
                     + gr_s[ub * 4 + 2] + gr_s[ub * 4 + 3];
            float z = 1.0f / (1.0f + __expf(-az));
            float r = 1.0f / (1.0f + __expf(-ar));
            float hold = h_sT[(h0 + uh) * 4 + ub];
            float arg = xn + m * r;
            arg = fminf(fmaxf(arg, -15.0f), 15.0f);
            float e2 = __expf(2.0f * arg);
            float n = 1.0f - 2.0f / (e2 + 1.0f);
            hreg = (1.0f - z) * n + z * hold;
            out[(size_t)t * BH + (size_t)(b0 + ub) * 512 + h0 + uh] = hreg;
        }

        // only same-cluster blocks consume out[t] -> HW cluster barrier suffices
        cluster_sync();
    }

    if (write_final)
        hfinal[(size_t)(b0 + ub) * 512 + h0 + uh] = hreg;
}

// ---------------- launcher ----------------
extern "C" void kernel_launch(void* const* d_in, const int* in_sizes, int n_in,
                              void* d_out, int out_size)
{
    const float* input  = (const float*)d_in[0];
    const float* hidden = (const float*)d_in[1];
    const float* zt_w_w = (const float*)d_in[2];
    const float* zt_w_b = (const float*)d_in[3];
    const float* zt_u_w = (const float*)d_in[4];
    const float* zt_u_b = (const float*)d_in[5];
    const float* rt_w_w = (const float*)d_in[6];
    const float* rt_w_b = (const float*)d_in[7];
    const float* rt_u_w = (const float*)d_in[8];
    const float* rt_u_b = (const float*)d_in[9];
    const float* h_w_w  = (const float*)d_in[10];
    const float* h_w_b  = (const float*)d_in[11];
    const float* h_u_w  = (const float*)d_in[12];
    const float* h_u_b  = (const float*)d_in[13];

    float* out = (float*)d_out;
    int wf = (out_size >= T_DIM * BH + BH) ? 1 : 0;
    float* hfin = out + (size_t)T_DIM * BH;

    cudaFuncSetAttribute(k_recur, cudaFuncAttributeMaxDynamicSharedMemorySize,
                         SMEM_BYTES);

    k_xn<<<dim3(8, 512), 256>>>(input, h_w_w, h_w_b, out);
    k_recur<<<NBLK, 256, SMEM_BYTES>>>(input, hidden,
                                       zt_w_w, zt_w_b, zt_u_w, zt_u_b,
                                       rt_w_w, rt_w_b, rt_u_w, rt_u_b,
                                       h_u_w, h_u_b, out, hfin, wf);
}

// round 11
// speedup vs baseline: 1.8583x; 1.8583x over previous
#include <cuda_runtime.h>
#include <math.h>

#define T_DIM 512
#define B_DIM 64
#define I_DIM 512
#define H_DIM 512
#define BH (B_DIM * H_DIM)          // 32768
#define NBLK 128
#define NGRP 16                      // b-groups (4 rows each), 8 blocks per group

// SMEM float offsets (dynamic shared)
#define W_OFF   0                    // 512*68 = 34816 (weight slice, transposed, padded)
#define H_OFF   34816                // 4*520  = 2080  (h rows)
#define RED_OFF 36896                // 16*4*64 = 4096 (k-partials; reused for zw/rw in preamble)
#define ZU_OFF  40992                // 512
#define RU_OFF  41504                // 512
#define XZ_OFF  42016                // 2048 ([t*4+b])
#define XR_OFF  44064                // 2048
#define GZ_OFF  46112                // 64 ([b*16+kc])
#define GR_OFF  46176                // 64
#define SMEM_FLOATS 46240
#define SMEM_BYTES (SMEM_FLOATS * 4) // 184960

typedef unsigned long long ull;

// ---------------- scratch ----------------
__device__ float g_xz[T_DIM * B_DIM];
__device__ float g_xr[T_DIM * B_DIM];
__device__ unsigned int g_gctr[NGRP * 32];   // one 128B line per b-group

// ---------------- packed f32x2 helpers ----------------
static __device__ __forceinline__ ull pk2(float x) {
    ull r;
    asm("mov.b64 %0, {%1, %1};" : "=l"(r) : "f"(x));
    return r;
}
static __device__ __forceinline__ void fma2(ull& d, ull a, ull b) {
    asm("fma.rn.f32x2 %0, %1, %2, %0;" : "+l"(d) : "l"(a), "l"(b));
}
static __device__ __forceinline__ void unpk(ull v, float& lo, float& hi) {
    asm("mov.b64 {%0, %1}, %2;" : "=f"(lo), "=f"(hi) : "l"(v));
}

// ---------------- per-group barrier primitives ----------------
static __device__ __forceinline__ void arrive_rel(unsigned int* p) {
    asm volatile("red.release.gpu.global.add.u32 [%0], 1;" :: "l"(p) : "memory");
}
static __device__ __forceinline__ unsigned int ld_acq(unsigned int* p) {
    unsigned int v;
    asm volatile("ld.acquire.gpu.global.u32 %0, [%1];" : "=r"(v) : "l"(p) : "memory");
    return v;
}
// group barrier: couples only the 8 blocks of one b-group
static __device__ __forceinline__ void ggsync(unsigned int* ctr, int tid,
                                              unsigned int target) {
    __syncthreads();
    if (tid == 0) {
        arrive_rel(ctr);
        while (ld_acq(ctr) < target) { }
    }
    __syncthreads();
}

// ---------------- K1: xn = input @ h_w_w^T + h_w_b -> out[t] ----------------
__global__ __launch_bounds__(256) void k_xn(
    const float* __restrict__ A,
    const float* __restrict__ W,
    const float* __restrict__ bias,
    float* __restrict__ C)
{
    __shared__ float As[64 * 17];
    __shared__ float Bs[16 * 64];
    const int bm = blockIdx.y * 64;
    const int bn = blockIdx.x * 64;
    const int tid = threadIdx.x;
    const int tx = tid & 15;
    const int ty = tid >> 4;
    const int r0 = tid >> 2;
    const int c4 = (tid & 3) * 4;

    ull acc[4][2] = {};

    const float* Ap = A + (size_t)(bm + r0) * 512 + c4;
    const float* Wp = W + (size_t)(bn + r0) * 512 + c4;
    float4 a0 = *(const float4*)Ap;
    float4 w0 = *(const float4*)Wp;

    for (int kt = 0; kt < 32; kt++) {
        As[r0 * 17 + c4 + 0] = a0.x;  As[r0 * 17 + c4 + 1] = a0.y;
        As[r0 * 17 + c4 + 2] = a0.z;  As[r0 * 17 + c4 + 3] = a0.w;
        Bs[(c4 + 0) * 64 + r0] = w0.x;  Bs[(c4 + 1) * 64 + r0] = w0.y;
        Bs[(c4 + 2) * 64 + r0] = w0.z;  Bs[(c4 + 3) * 64 + r0] = w0.w;
        __syncthreads();
        if (kt < 31) {
            a0 = *(const float4*)(Ap + (kt + 1) * 16);
            w0 = *(const float4*)(Wp + (kt + 1) * 16);
        }
#pragma unroll
        for (int k = 0; k < 16; k++) {
            ulonglong2 b2 = *(ulonglong2*)&Bs[k * 64 + tx * 4];
#pragma unroll
            for (int i = 0; i < 4; i++) {
                ull aa = pk2(As[(ty * 4 + i) * 17 + k]);
                fma2(acc[i][0], aa, b2.x);
                fma2(acc[i][1], aa, b2.y);
            }
        }
        __syncthreads();
    }
    float4 bv = *(const float4*)(bias + bn + tx * 4);
#pragma unroll
    for (int i = 0; i < 4; i++) {
        float x0, x1, x2, x3;
        unpk(acc[i][0], x0, x1);
        unpk(acc[i][1], x2, x3);
        float4 o = make_float4(x0 + bv.x, x1 + bv.y, x2 + bv.z, x3 + bv.w);
        *(float4*)(C + (size_t)(bm + ty * 4 + i) * 512 + bn + tx * 4) = o;
    }
}

// ---------------- K2: persistent recurrent scan (per-group barrier) ----------------
// 128 blocks = 16 b-groups (4 rows) x 8 h-slices (64 cols). Each block computes its
// (4b x 64h) tile with FULL K=512 (split-K inside the block via SMEM reduce).
// Only same-group blocks exchange h_t -> barrier couples just 8 blocks.
__global__ __launch_bounds__(256, 1) void k_recur(
    const float* __restrict__ input,
    const float* __restrict__ hidden,
    const float* __restrict__ zw_w, const float* __restrict__ zw_b,
    const float* __restrict__ zu_w, const float* __restrict__ zu_b,
    const float* __restrict__ rw_w, const float* __restrict__ rw_b,
    const float* __restrict__ ru_w, const float* __restrict__ ru_b,
    const float* __restrict__ hu_w, const float* __restrict__ hu_b,
    float* __restrict__ out,          // [T][B][H]: xn on entry, h_t on exit
    float* __restrict__ hfinal, int write_final)
{
    extern __shared__ float smem[];
    float* w_s   = smem + W_OFF;      // [k][j] j=0..63, stride 68
    float* h_s   = smem + H_OFF;      // [b][k] stride 520
    float* red_s = smem + RED_OFF;    // [kc][b][h] 16x4x64
    float* zu_s  = smem + ZU_OFF;
    float* ru_s  = smem + RU_OFF;
    float* xz_s  = smem + XZ_OFF;     // [t*4+b]
    float* xr_s  = smem + XR_OFF;
    float* gz_s  = smem + GZ_OFF;     // [b*16+kc]
    float* gr_s  = smem + GR_OFF;

    const int tid = threadIdx.x;
    const int bid = blockIdx.x;
    const int bg = bid >> 3;          // b-group: rows [bg*4, bg*4+4)
    const int hg = bid & 7;           // h-slice: cols [hg*64, hg*64+64)
    const int b0 = bg * 4;
    const int h0 = hg * 64;
    const int kcg = tid >> 4;         // k-chunk 0..15 (32 k each)
    const int tx = tid & 15;          // h-quad 0..15
    unsigned int* gctr = &g_gctr[bg * 32];

    // persistent weight slice (transposed): w_s[k*68 + j] = hu_w[h0+j][k]
    for (int e = tid; e < 32768; e += 256) {
        int j = e >> 9, k = e & 511;
        w_s[k * 68 + j] = hu_w[(size_t)(h0 + j) * 512 + k];
    }
    for (int e = tid; e < 512; e += 256) {
        zu_s[e] = zu_w[e];
        ru_s[e] = ru_w[e];
    }
    const float zub = zu_b[0], rub = ru_b[0];
    const float zwb = zw_b[0], rwb = rw_b[0];

    // preamble: hg==0 blocks compute xz/xr for their 4 b-rows, all t
    if (hg == 0) {
        float* zw_s = red_s;          // reuse reduce buffer
        float* rw_s = red_s + 512;
        for (int e = tid; e < 512; e += 256) {
            zw_s[e] = zw_w[e];
            rw_s[e] = rw_w[e];
        }
        __syncthreads();
        for (int e = tid; e < 2048; e += 256) {
            int t = e >> 2, b = e & 3;
            const float4* ip = (const float4*)(input + ((size_t)t * 64 + b0 + b) * 512);
            float az = 0.f, ar = 0.f;
#pragma unroll 8
            for (int i = 0; i < 128; i++) {
                float4 v = ip[i];
                float4 zz = *(float4*)&zw_s[i * 4];
                float4 rr = *(float4*)&rw_s[i * 4];
                az += v.x * zz.x + v.y * zz.y + v.z * zz.z + v.w * zz.w;
                ar += v.x * rr.x + v.y * rr.y + v.z * rr.z + v.w * rr.w;
            }
            g_xz[t * 64 + b0 + b] = az + zwb;
            g_xr[t * 64 + b0 + b] = ar + rwb;
        }
    }
    ggsync(gctr, tid, 8);             // preamble barrier (group-local)

    // copy this block's gate-x slice to SMEM
    for (int e = tid; e < 2048; e += 256) {
        int t = e >> 2, b = e & 3;
        xz_s[e] = __ldcg(&g_xz[t * 64 + b0 + b]);
        xr_s[e] = __ldcg(&g_xr[t * 64 + b0 + b]);
    }

    // update-element constants (thread owns element (ub, uh) of the tile)
    const int ub = tid >> 6;          // 0..3
    const int uh = tid & 63;          // 0..63
    const float hub = hu_b[h0 + uh];
    float hreg = 0.f;
    __syncthreads();

    for (int t = 0; t < T_DIM; t++) {
        const float* hprev = (t == 0) ? hidden : (out + (size_t)(t - 1) * BH);

        // prefetch this thread's xn
        float xn = __ldcg(out + (size_t)t * BH + (size_t)(b0 + ub) * 512 + h0 + uh);

        // phase 1: load h rows [4 b][512 k] (512 float4, 2 per thread)
#pragma unroll
        for (int i = 0; i < 2; i++) {
            int e4 = tid + i * 256;
            int b = e4 >> 7, kq = e4 & 127;
            float4 v = __ldcg((const float4*)(hprev + (size_t)(b0 + b) * 512 + kq * 4));
            *(float4*)&h_s[b * 520 + kq * 4] = v;
        }
        __syncthreads();

        // phase 2a: gate-u partials (64 threads: (b, kc))
        if (tid < 64) {
            int b = tid & 3, kc2 = tid >> 2;
            float az = 0.f, ar = 0.f;
#pragma unroll
            for (int k = kc2 * 32; k < kc2 * 32 + 32; k++) {
                float hv = h_s[b * 520 + k];
                az += hv * zu_s[k];
                ar += hv * ru_s[k];
            }
            gz_s[b * 16 + kc2] = az;
            gr_s[b * 16 + kc2] = ar;
        }

        // phase 2b: matvec 4b x 4h x 32k per thread (f32x2)
        {
            ull acc[4][2] = {};
            const int kb = kcg * 32;
#pragma unroll
            for (int k = 0; k < 32; k++) {
                ulonglong2 w2 = *(ulonglong2*)&w_s[(kb + k) * 68 + tx * 4];
                ull h0p = pk2(h_s[0 * 520 + kb + k]);
                ull h1p = pk2(h_s[1 * 520 + kb + k]);
                ull h2p = pk2(h_s[2 * 520 + kb + k]);
                ull h3p = pk2(h_s[3 * 520 + kb + k]);
                fma2(acc[0][0], h0p, w2.x); fma2(acc[0][1], h0p, w2.y);
                fma2(acc[1][0], h1p, w2.x); fma2(acc[1][1], h1p, w2.y);
                fma2(acc[2][0], h2p, w2.x); fma2(acc[2][1], h2p, w2.y);
                fma2(acc[3][0], h3p, w2.x); fma2(acc[3][1], h3p, w2.y);
            }
#pragma unroll
            for (int b = 0; b < 4; b++) {
                float x0, x1, x2, x3;
                unpk(acc[b][0], x0, x1);
                unpk(acc[b][1], x2, x3);
                *(float4*)&red_s[kcg * 256 + b * 64 + tx * 4] =
                    make_float4(x0, x1, x2, x3);
            }
        }
        __syncthreads();

        // phase 3: reduce k-partials + gates + update (1 element/thread)
        {
            float m = hub;
#pragma unroll
            for (int kc = 0; kc < 16; kc++)
                m += red_s[kc * 256 + ub * 64 + uh];
            float az = xz_s[t * 4 + ub] + zub;
            float ar = xr_s[t * 4 + ub] + rub;
#pragma unroll
            for (int kc = 0; kc < 16; kc++) {
                az += gz_s[ub * 16 + kc];
                ar += gr_s[ub * 16 + kc];
            }
            float z = 1.0f / (1.0f + __expf(-az));
            float r = 1.0f / (1.0f + __expf(-ar));
            float hold = h_s[ub * 520 + h0 + uh];
            float arg = xn + m * r;
            arg = fminf(fmaxf(arg, -15.0f), 15.0f);
            float e2 = __expf(2.0f * arg);
            float n = 1.0f - 2.0f / (e2 + 1.0f);
            hreg = (1.0f - z) * n + z * hold;
            out[(size_t)t * BH + (size_t)(b0 + ub) * 512 + h0 + uh] = hreg;
        }

        ggsync(gctr, tid, (unsigned int)8 * (t + 2));
    }

    if (write_final)
        hfinal[(size_t)(b0 + ub) * 512 + h0 + uh] = hreg;

    // final arrival + per-group counter reset for graph replay
    // total arrivals per group: 8 (preamble) + 8*T (steps) + 8 (final) = 8*(T+2)
    __syncthreads();
    if (tid == 0) {
        arrive_rel(gctr);
        if (hg == 0) {
            unsigned int fin = (unsigned int)8 * (T_DIM + 2);
            while (ld_acq(gctr) < fin) { }
            asm volatile("st.relaxed.gpu.global.u32 [%0], 0;" :: "l"(gctr) : "memory");
        }
    }
}

// ---------------- launcher ----------------
extern "C" void kernel_launch(void* const* d_in, const int* in_sizes, int n_in,
                              void* d_out, int out_size)
{
    const float* input  = (const float*)d_in[0];
    const float* hidden = (const float*)d_in[1];
    const float* zt_w_w = (const float*)d_in[2];
    const float* zt_w_b = (const float*)d_in[3];
    const float* zt_u_w = (const float*)d_in[4];
    const float* zt_u_b = (const float*)d_in[5];
    const float* rt_w_w = (const float*)d_in[6];
    const float* rt_w_b = (const float*)d_in[7];
    const float* rt_u_w = (const float*)d_in[8];
    const float* rt_u_b = (const float*)d_in[9];
    const float* h_w_w  = (const float*)d_in[10];
    const float* h_w_b  = (const float*)d_in[11];
    const float* h_u_w  = (const float*)d_in[12];
    const float* h_u_b  = (const float*)d_in[13];

    float* out = (float*)d_out;
    int wf = (out_size >= T_DIM * BH + BH) ? 1 : 0;
    float* hfin = out + (size_t)T_DIM * BH;

    cudaFuncSetAttribute(k_recur, cudaFuncAttributeMaxDynamicSharedMemorySize,
                         SMEM_BYTES);

    k_xn<<<dim3(8, 512), 256>>>(input, h_w_w, h_w_b, out);
    k_recur<<<NBLK, 256, SMEM_BYTES>>>(input, hidden,
                                       zt_w_w, zt_w_b, zt_u_w, zt_u_b,
                                       rt_w_w, rt_w_b, rt_u_w, rt_u_b,
                                       h_u_w, h_u_b, out, hfin, wf);
}